// round 8
// baseline (speedup 1.0000x reference)
#include <cuda_runtime.h>
#include <cstdint>

// SimpleGNN: 3x CGConv + mean-pool + linear.
// P[N,512] = H @ B^T (node projections, biases folded into dst halves).
// Edge-attr projection (K=16) per-edge with register-resident weights:
// 1 channel/lane, warp-task = (node, quarter), f32x2 packed FMA.
// R8: 2-stage software pipeline in node_k — srcp prefetched 2 edges ahead,
// P-gathers + ew prefetched 1 edge ahead — to hide the dependent-gather latency
// that made R7 stall-bound (IPC~0.2).

#define NN 50000
#define EE 800000
#define CC 128
#define ZP 512

typedef unsigned long long ull;

__device__ __align__(16) float g_P[(size_t)NN * ZP];   // node projections (+bias on dst halves)
__device__ __align__(16) float g_hA[(size_t)NN * CC];
__device__ __align__(16) float g_hB[(size_t)NN * CC];
__device__ __align__(16) float g_B[ZP * CC];           // packed node-projection weights
__device__ float g_cs[CC];                 // column sums for pooling
__device__ int   g_idx64;                  // 1 if edge_idx is int64, 0 if int32
__device__ int   g_start[NN + 1];          // CSR row offsets (by dst)
__device__ int   g_cur[NN];                // histogram / scatter cursor
__device__ int   g_srcp[EE];               // CSR: src node per slot
__device__ __align__(16) float g_ewc[(size_t)EE * 16]; // ew permuted into CSR order
__device__ int   g_bsum[256];              // scan block sums
__device__ int   g_boff[256];              // scan block offsets

// ---- f32x2 helpers (sm_100+) ----------------------------------------------
__device__ __forceinline__ void unpack2(ull v, float& a, float& b) {
    asm("mov.b64 {%0, %1}, %2;" : "=f"(a), "=f"(b) : "l"(v));
}
__device__ __forceinline__ ull fma2(ull a, ull b, ull c) {
    ull d; asm("fma.rn.f32x2 %0, %1, %2, %3;" : "=l"(d) : "l"(a), "l"(b), "l"(c));
    return d;
}

// ---------------------------------------------------------------------------
__global__ void detect_k(const long long* __restrict__ e64, int N) {
    if (threadIdx.x == 0 && blockIdx.x == 0) {
        int ok64 = 1;
        for (int i = 0; i < 64; i++) {
            long long v = e64[i];
            if (v < 0 || v >= N) { ok64 = 0; break; }
        }
        g_idx64 = ok64;
    }
}

__device__ __forceinline__ int load_idx(const void* p, long long off) {
    return g_idx64 ? (int)__ldg((const long long*)p + off)
                   : __ldg((const int*)p + off);
}

// ---------------------------------------------------------------------------
__global__ void zero_int_k(int* __restrict__ p, int n) {
    for (int i = blockIdx.x * blockDim.x + threadIdx.x; i < n;
         i += gridDim.x * blockDim.x) p[i] = 0;
}

__global__ void count_k(const void* __restrict__ eidx, int E) {
    for (int e = blockIdx.x * blockDim.x + threadIdx.x; e < E;
         e += gridDim.x * blockDim.x) {
        int d = load_idx(eidx, (long long)E + e);
        atomicAdd(&g_cur[d], 1);
    }
}

// hierarchical scan
__global__ void scan1_k(int N) {
    __shared__ int sh[256];
    int t = threadIdx.x;
    int i = blockIdx.x * 256 + t;
    int v = (i < N) ? g_cur[i] : 0;
    sh[t] = v;
    __syncthreads();
#pragma unroll
    for (int off = 1; off < 256; off <<= 1) {
        int u = (t >= off) ? sh[t - off] : 0;
        __syncthreads();
        sh[t] += u;
        __syncthreads();
    }
    if (i < N) g_start[i] = sh[t] - v;
    if (t == 255) g_bsum[blockIdx.x] = sh[255];
}

__global__ void scan2_k(int nblk) {
    __shared__ int sh[256];
    int t = threadIdx.x;
    int v = (t < nblk) ? g_bsum[t] : 0;
    sh[t] = v;
    __syncthreads();
#pragma unroll
    for (int off = 1; off < 256; off <<= 1) {
        int u = (t >= off) ? sh[t - off] : 0;
        __syncthreads();
        sh[t] += u;
        __syncthreads();
    }
    g_boff[t] = sh[t] - v;
}

__global__ void scan3_k(int N, int E) {
    int i = blockIdx.x * blockDim.x + threadIdx.x;
    if (i < N) {
        g_start[i] += g_boff[i >> 8];
        g_cur[i] = 0;
    }
    if (i == 0) g_start[N] = E;
}

// scatter: CSR src list + permute ew into CSR order (64B per edge)
__global__ void scatter_k(const void* __restrict__ eidx,
                          const float* __restrict__ ew, int E) {
    for (int e = blockIdx.x * blockDim.x + threadIdx.x; e < E;
         e += gridDim.x * blockDim.x) {
        int s = load_idx(eidx, e);
        int d = load_idx(eidx, (long long)E + e);
        int pos = g_start[d] + atomicAdd(&g_cur[d], 1);
        g_srcp[pos] = s;
        const float4* src4 = (const float4*)(ew + (size_t)e * 16);
        float4* dst4 = (float4*)(g_ewc + (size_t)pos * 16);
        dst4[0] = src4[0]; dst4[1] = src4[1];
        dst4[2] = src4[2]; dst4[3] = src4[3];
    }
}

// ---------------------------------------------------------------------------
// pack the 512x128 node-projection weight matrix
__global__ void pack_B(const float* __restrict__ Wf, const float* __restrict__ Ws) {
    int j = blockIdx.x * blockDim.x + threadIdx.x;
    if (j >= ZP * CC) return;
    int row  = j >> 7;
    int k    = j & 127;
    int c    = row & 127;
    int part = row >> 7;
    const float* W = (part < 2) ? Wf : Ws;
    int off = (part & 1) ? 128 : 0;
    g_B[j] = W[c * 272 + off + k];
}

// ---------------------------------------------------------------------------
// P[M,512] = H[M,128] @ g_B^T ; bias folded into dst halves.
__global__ void gemm_k(const float* __restrict__ H,
                       const float* __restrict__ bf,
                       const float* __restrict__ bs, int M) {
    __shared__ float As[32][65];
    __shared__ float Bs[32][65];
    int tid = threadIdx.x;
    int tx = tid & 15, ty = tid >> 4;
    int i0 = blockIdx.x * 64, j0 = blockIdx.y * 64;

    float acc[4][4];
#pragma unroll
    for (int r = 0; r < 4; r++)
#pragma unroll
        for (int p = 0; p < 4; p++) acc[r][p] = 0.f;

    for (int k0 = 0; k0 < 128; k0 += 32) {
#pragma unroll
        for (int rep = 0; rep < 2; rep++) {
            int ii = (tid >> 3) + rep * 32;
            int kk = (tid & 7) << 2;
            int row = i0 + ii;
            float4 va = make_float4(0.f, 0.f, 0.f, 0.f);
            if (row < M) va = *(const float4*)(H + (size_t)row * 128 + k0 + kk);
            As[kk + 0][ii] = va.x; As[kk + 1][ii] = va.y;
            As[kk + 2][ii] = va.z; As[kk + 3][ii] = va.w;
            float4 vb = *(const float4*)(g_B + (size_t)(j0 + ii) * 128 + k0 + kk);
            Bs[kk + 0][ii] = vb.x; Bs[kk + 1][ii] = vb.y;
            Bs[kk + 2][ii] = vb.z; Bs[kk + 3][ii] = vb.w;
        }
        __syncthreads();
#pragma unroll
        for (int kk = 0; kk < 32; kk++) {
            float a[4], b[4];
#pragma unroll
            for (int r = 0; r < 4; r++) a[r] = As[kk][ty * 4 + r];
#pragma unroll
            for (int p = 0; p < 4; p++) b[p] = Bs[kk][tx * 4 + p];
#pragma unroll
            for (int r = 0; r < 4; r++)
#pragma unroll
                for (int p = 0; p < 4; p++) acc[r][p] = fmaf(a[r], b[p], acc[r][p]);
        }
        __syncthreads();
    }

    int col = j0 + tx * 4;
    float4 badd = make_float4(0.f, 0.f, 0.f, 0.f);
    if (col < 128)                badd = *(const float4*)(bf + col);
    else if (col >= 256 && col < 384) badd = *(const float4*)(bs + col - 256);

#pragma unroll
    for (int r = 0; r < 4; r++) {
        int row = i0 + ty * 4 + r;
        if (row < M)
            *(float4*)(g_P + (size_t)row * ZP + col) =
                make_float4(acc[r][0] + badd.x, acc[r][1] + badd.y,
                            acc[r][2] + badd.z, acc[r][3] + badd.w);
    }
}

// ---------------------------------------------------------------------------
__global__ void zero_k(float* __restrict__ p, int n4) {
    float4* q = (float4*)p;
    for (int i = blockIdx.x * blockDim.x + threadIdx.x; i < n4;
         i += gridDim.x * blockDim.x)
        q[i] = make_float4(0.f, 0.f, 0.f, 0.f);
}

__device__ __forceinline__ float sigm(float x) {
    return __fdividef(1.f, 1.f + __expf(-x));
}
__device__ __forceinline__ float sftp(float x) {
    return fmaxf(x, 0.f) + __logf(1.f + __expf(-fabsf(x)));
}

// ---------------------------------------------------------------------------
// Warp task = (node, quarter). Lane owns channel c = 32*q + lane.
// 2-stage pipeline: srcp prefetched 2 edges ahead, gathers + ew 1 edge ahead.
__global__ void node_k(const float* __restrict__ hin, float* __restrict__ hout,
                       const float* __restrict__ Wf, const float* __restrict__ Ws,
                       int M, int relu) {
    int lane = threadIdx.x & 31;
    int wg   = blockIdx.x * (blockDim.x >> 5) + (threadIdx.x >> 5);
    int nwg  = gridDim.x * (blockDim.x >> 5);   // multiple of 4 by construction
    int q    = wg & 3;
    int c    = q * 32 + lane;                   // this lane's channel

    // register-resident K-weights: 8 f32x2 per gate
    ull wf2[8], ws2[8];
    {
        const ulonglong2* wfp = (const ulonglong2*)(Wf + (size_t)c * 272 + 256);
        const ulonglong2* wsp = (const ulonglong2*)(Ws + (size_t)c * 272 + 256);
#pragma unroll
        for (int i = 0; i < 4; i++) {
            ulonglong2 a = __ldg(wfp + i);
            wf2[2 * i] = a.x; wf2[2 * i + 1] = a.y;
            ulonglong2 b = __ldg(wsp + i);
            ws2[2 * i] = b.x; ws2[2 * i + 1] = b.y;
        }
    }

    for (int n = wg >> 2; n < M; n += nwg >> 2) {
        const float* Pd = g_P + (size_t)n * ZP;
        float fd = __ldg(Pd + c);          // dst f (bias folded)
        float sd = __ldg(Pd + 256 + c);    // dst s (bias folded)
        float m = 0.f;

        int j0 = __ldg(g_start + n), j1 = __ldg(g_start + n + 1);
        if (j0 < j1) {
            // ---- pipeline prologue: stage edge j0, src index for j0+1 ----
            int s1 = __ldg(g_srcp + j0);
            const ulonglong2* ep = (const ulonglong2*)(g_ewc + (size_t)j0 * 16);
            ulonglong2 ea = __ldg(ep + 0), eb = __ldg(ep + 1);
            ulonglong2 ec = __ldg(ep + 2), ed = __ldg(ep + 3);
            float fs1 = __ldg(g_P + (size_t)s1 * ZP + 128 + c);
            float ss1 = __ldg(g_P + (size_t)s1 * ZP + 384 + c);
            int s2 = (j0 + 1 < j1) ? __ldg(g_srcp + j0 + 1) : 0;

            for (int j = j0; j < j1; j++) {
                // consume stage
                float fs = fs1, ss = ss1;
                ull x0 = ea.x, x1 = ea.y, x2 = eb.x, x3 = eb.y;
                ull x4 = ec.x, x5 = ec.y, x6 = ed.x, x7 = ed.y;

                // prefetch next edge (gathers for j+1 via s2, srcp for j+2)
                if (j + 1 < j1) {
                    const ulonglong2* ep2 =
                        (const ulonglong2*)(g_ewc + (size_t)(j + 1) * 16);
                    ea = __ldg(ep2 + 0); eb = __ldg(ep2 + 1);
                    ec = __ldg(ep2 + 2); ed = __ldg(ep2 + 3);
                    fs1 = __ldg(g_P + (size_t)s2 * ZP + 128 + c);
                    ss1 = __ldg(g_P + (size_t)s2 * ZP + 384 + c);
                    s2 = (j + 2 < j1) ? __ldg(g_srcp + j + 2) : 0;
                }

                // compute edge j
                ull FF = 0, SS = 0;   // (0.f, 0.f) packed
                FF = fma2(x0, wf2[0], FF);  SS = fma2(x0, ws2[0], SS);
                FF = fma2(x1, wf2[1], FF);  SS = fma2(x1, ws2[1], SS);
                FF = fma2(x2, wf2[2], FF);  SS = fma2(x2, ws2[2], SS);
                FF = fma2(x3, wf2[3], FF);  SS = fma2(x3, ws2[3], SS);
                FF = fma2(x4, wf2[4], FF);  SS = fma2(x4, ws2[4], SS);
                FF = fma2(x5, wf2[5], FF);  SS = fma2(x5, ws2[5], SS);
                FF = fma2(x6, wf2[6], FF);  SS = fma2(x6, ws2[6], SS);
                FF = fma2(x7, wf2[7], FF);  SS = fma2(x7, ws2[7], SS);

                float flo, fhi, slo, shi;
                unpack2(FF, flo, fhi);
                unpack2(SS, slo, shi);
                float F = fd + fs + flo + fhi;
                float S = sd + ss + slo + shi;
                m += sigm(F) * sftp(S);
            }
        }

        float hv = hin[(size_t)n * CC + c] + m;
        if (relu) hv = fmaxf(hv, 0.f);
        hout[(size_t)n * CC + c] = hv;
    }
}

// ---------------------------------------------------------------------------
__global__ void colsum_k(const float* __restrict__ h, int M) {
    int c = threadIdx.x;   // 128 threads
    float loc = 0.f;
    for (int i = blockIdx.x; i < M; i += gridDim.x)
        loc += h[(size_t)i * CC + c];
    atomicAdd(&g_cs[c], loc);
}

__global__ void final_k(const float* __restrict__ Wlin,
                        const float* __restrict__ blin,
                        float* __restrict__ out, float invM) {
    int o = threadIdx.x;
    if (o < 64) {
        float a = 0.f;
#pragma unroll 4
        for (int c = 0; c < 128; c++) a += g_cs[c] * Wlin[o * 128 + c];
        out[o] = blin[o] + a * invM;
    }
}

// ---------------------------------------------------------------------------
extern "C" void kernel_launch(void* const* d_in, const int* in_sizes, int n_in,
                              void* d_out, int out_size) {
    const float* x    = (const float*)d_in[0];
    const void*  eidx = d_in[1];
    const float* ew   = (const float*)d_in[2];
    const float* Wf[3] = {(const float*)d_in[3], (const float*)d_in[7],  (const float*)d_in[11]};
    const float* bf[3] = {(const float*)d_in[4], (const float*)d_in[8],  (const float*)d_in[12]};
    const float* Ws[3] = {(const float*)d_in[5], (const float*)d_in[9],  (const float*)d_in[13]};
    const float* bs[3] = {(const float*)d_in[6], (const float*)d_in[10], (const float*)d_in[14]};
    const float* Wlin = (const float*)d_in[15];
    const float* blin = (const float*)d_in[16];
    float* out = (float*)d_out;

    int M = in_sizes[0] / 128;   // 50000
    int E = in_sizes[2] / 16;    // 800000

    float *hA, *hB, *cs;
    int *cur;
    cudaGetSymbolAddress((void**)&hA,  g_hA);
    cudaGetSymbolAddress((void**)&hB,  g_hB);
    cudaGetSymbolAddress((void**)&cs,  g_cs);
    cudaGetSymbolAddress((void**)&cur, g_cur);

    const float* hin[3]  = {x, hA, hB};
    float*       hout[3] = {hA, hB, hA};

    dim3 ggrid((M + 63) / 64, 8);
    int nblk = (M + 255) / 256;

    // ---- CSR build (once per launch) ----
    detect_k<<<1, 32>>>((const long long*)eidx, M);
    zero_int_k<<<256, 256>>>(cur, M);
    count_k<<<1024, 256>>>(eidx, E);
    scan1_k<<<nblk, 256>>>(M);
    scan2_k<<<1, 256>>>(nblk);
    scan3_k<<<nblk, 256>>>(M, E);
    scatter_k<<<1024, 256>>>(eidx, ew, E);

    // ---- 3 CGConv layers ----
    for (int l = 0; l < 3; l++) {
        pack_B<<<(ZP * CC + 255) / 256, 256>>>(Wf[l], Ws[l]);
        gemm_k<<<ggrid, 256>>>(hin[l], bf[l], bs[l], M);
        // 4*M warp tasks, 8 warps per block
        node_k<<<(4 * M + 7) / 8, 256>>>(hin[l], hout[l], Wf[l], Ws[l],
                                         M, (l < 2) ? 1 : 0);
    }

    // ---- mean pool + linear ----
    zero_k<<<1, 32>>>(cs, CC / 4);
    colsum_k<<<512, 128>>>(hA, M);
    final_k<<<1, 64>>>(Wlin, blin, out, 1.0f / (float)M);
}

// round 9
// speedup vs baseline: 1.2631x; 1.2631x over previous
#include <cuda_runtime.h>
#include <cstdint>

// SimpleGNN: 3x CGConv + mean-pool + linear.
// P[N,512] = H @ B^T (one GEMM/layer, biases folded into dst halves).
// R9: EDGE-PARALLEL message pass (all edges independent -> full MLP, no serial
// chains) with REGISTER-resident K=16 edge-attr weights (1 channel/lane,
// warp-task = (edge, quarter), f32x2 packed FMA) and coalesced scalar
// red.global.add.f32 scatter. No CSR, no smem in the hot loop.

#define NN 50000
#define EE 800000
#define CC 128
#define ZP 512

typedef unsigned long long ull;

__device__ __align__(16) float g_P[(size_t)NN * ZP];   // node projections (+bias on dst halves)
__device__ __align__(16) float g_hA[(size_t)NN * CC];
__device__ __align__(16) float g_hB[(size_t)NN * CC];
__device__ __align__(16) float g_msg[(size_t)NN * CC]; // aggregated messages
__device__ __align__(16) float g_B[ZP * CC];           // packed node-projection weights
__device__ float g_cs[CC];                 // column sums for pooling
__device__ int   g_idx64;                  // 1 if edge_idx is int64, 0 if int32

// ---- f32x2 helpers (sm_100+) ----------------------------------------------
__device__ __forceinline__ void unpack2(ull v, float& a, float& b) {
    asm("mov.b64 {%0, %1}, %2;" : "=f"(a), "=f"(b) : "l"(v));
}
__device__ __forceinline__ ull fma2(ull a, ull b, ull c) {
    ull d; asm("fma.rn.f32x2 %0, %1, %2, %3;" : "=l"(d) : "l"(a), "l"(b), "l"(c));
    return d;
}

// ---------------------------------------------------------------------------
__global__ void detect_k(const long long* __restrict__ e64, int N) {
    if (threadIdx.x == 0 && blockIdx.x == 0) {
        int ok64 = 1;
        for (int i = 0; i < 64; i++) {
            long long v = e64[i];
            if (v < 0 || v >= N) { ok64 = 0; break; }
        }
        g_idx64 = ok64;
    }
}

__device__ __forceinline__ int load_idx(const void* p, long long off) {
    return g_idx64 ? (int)__ldg((const long long*)p + off)
                   : __ldg((const int*)p + off);
}

// ---------------------------------------------------------------------------
// pack the 512x128 node-projection weight matrix:
// rows   0..127 : Wf[:,   0:128] (dst f) | 128..255 : Wf[:,128:256] (src f)
// rows 256..383 : Ws[:,   0:128] (dst s) | 384..511 : Ws[:,128:256] (src s)
__global__ void pack_B(const float* __restrict__ Wf, const float* __restrict__ Ws) {
    int j = blockIdx.x * blockDim.x + threadIdx.x;
    if (j >= ZP * CC) return;
    int row  = j >> 7;
    int k    = j & 127;
    int c    = row & 127;
    int part = row >> 7;
    const float* W = (part < 2) ? Wf : Ws;
    int off = (part & 1) ? 128 : 0;
    g_B[j] = W[c * 272 + off + k];
}

// ---------------------------------------------------------------------------
// P[M,512] = H[M,128] @ g_B^T ; bias folded into dst halves (cols 0:128 += bf,
// cols 256:384 += bs). fp32 tiled 64x64, 256 threads, 4x4 per thread.
__global__ void gemm_k(const float* __restrict__ H,
                       const float* __restrict__ bf,
                       const float* __restrict__ bs, int M) {
    __shared__ float As[32][65];
    __shared__ float Bs[32][65];
    int tid = threadIdx.x;
    int tx = tid & 15, ty = tid >> 4;
    int i0 = blockIdx.x * 64, j0 = blockIdx.y * 64;

    float acc[4][4];
#pragma unroll
    for (int r = 0; r < 4; r++)
#pragma unroll
        for (int p = 0; p < 4; p++) acc[r][p] = 0.f;

    for (int k0 = 0; k0 < 128; k0 += 32) {
#pragma unroll
        for (int rep = 0; rep < 2; rep++) {
            int ii = (tid >> 3) + rep * 32;
            int kk = (tid & 7) << 2;
            int row = i0 + ii;
            float4 va = make_float4(0.f, 0.f, 0.f, 0.f);
            if (row < M) va = *(const float4*)(H + (size_t)row * 128 + k0 + kk);
            As[kk + 0][ii] = va.x; As[kk + 1][ii] = va.y;
            As[kk + 2][ii] = va.z; As[kk + 3][ii] = va.w;
            float4 vb = *(const float4*)(g_B + (size_t)(j0 + ii) * 128 + k0 + kk);
            Bs[kk + 0][ii] = vb.x; Bs[kk + 1][ii] = vb.y;
            Bs[kk + 2][ii] = vb.z; Bs[kk + 3][ii] = vb.w;
        }
        __syncthreads();
#pragma unroll
        for (int kk = 0; kk < 32; kk++) {
            float a[4], b[4];
#pragma unroll
            for (int r = 0; r < 4; r++) a[r] = As[kk][ty * 4 + r];
#pragma unroll
            for (int p = 0; p < 4; p++) b[p] = Bs[kk][tx * 4 + p];
#pragma unroll
            for (int r = 0; r < 4; r++)
#pragma unroll
                for (int p = 0; p < 4; p++) acc[r][p] = fmaf(a[r], b[p], acc[r][p]);
        }
        __syncthreads();
    }

    int col = j0 + tx * 4;
    float4 badd = make_float4(0.f, 0.f, 0.f, 0.f);
    if (col < 128)                badd = *(const float4*)(bf + col);
    else if (col >= 256 && col < 384) badd = *(const float4*)(bs + col - 256);

#pragma unroll
    for (int r = 0; r < 4; r++) {
        int row = i0 + ty * 4 + r;
        if (row < M)
            *(float4*)(g_P + (size_t)row * ZP + col) =
                make_float4(acc[r][0] + badd.x, acc[r][1] + badd.y,
                            acc[r][2] + badd.z, acc[r][3] + badd.w);
    }
}

// ---------------------------------------------------------------------------
__global__ void zero_k(float* __restrict__ p, int n4) {
    float4* q = (float4*)p;
    for (int i = blockIdx.x * blockDim.x + threadIdx.x; i < n4;
         i += gridDim.x * blockDim.x)
        q[i] = make_float4(0.f, 0.f, 0.f, 0.f);
}

__device__ __forceinline__ float sigm(float x) {
    return __fdividef(1.f, 1.f + __expf(-x));
}
__device__ __forceinline__ float sftp(float x) {
    return fmaxf(x, 0.f) + __logf(1.f + __expf(-fabsf(x)));
}

// ---------------------------------------------------------------------------
// Warp task = (edge, quarter). Lane owns channel c = 32*q + lane.
// Weights: 16 f32x2 regs total (8 per gate), loaded once per persistent warp.
// Per edge: 2 idx LDG + 4 uniform ew LDG (packed f32x2 pairs) + 4 independent
// coalesced 128B P-gathers + 16 FFMA2 + activation + 1 coalesced scalar RED.
// All edges independent -> deep MLP, latency fully hidden.
__global__ void edge_k(const void* __restrict__ eidx,
                       const float* __restrict__ ew,
                       const float* __restrict__ Wf, const float* __restrict__ Ws,
                       int E) {
    int lane = threadIdx.x & 31;
    int wg   = blockIdx.x * (blockDim.x >> 5) + (threadIdx.x >> 5);
    int nwg  = gridDim.x * (blockDim.x >> 5);   // multiple of 4 by construction
    int q    = wg & 3;
    int c    = q * 32 + lane;                   // this lane's channel

    // register-resident K-weights: 8 f32x2 per gate (pairs along k)
    ull wf2[8], ws2[8];
    {
        const ulonglong2* wfp = (const ulonglong2*)(Wf + (size_t)c * 272 + 256);
        const ulonglong2* wsp = (const ulonglong2*)(Ws + (size_t)c * 272 + 256);
#pragma unroll
        for (int i = 0; i < 4; i++) {
            ulonglong2 a = __ldg(wfp + i);
            wf2[2 * i] = a.x; wf2[2 * i + 1] = a.y;
            ulonglong2 b = __ldg(wsp + i);
            ws2[2 * i] = b.x; ws2[2 * i + 1] = b.y;
        }
    }

    for (int e = wg >> 2; e < E; e += nwg >> 2) {
        int s = load_idx(eidx, e);
        int d = load_idx(eidx, (long long)E + e);

        const ulonglong2* ewp = (const ulonglong2*)(ew + (size_t)e * 16);
        ulonglong2 e0 = __ldg(ewp + 0), e1 = __ldg(ewp + 1);
        ulonglong2 e2 = __ldg(ewp + 2), e3 = __ldg(ewp + 3);

        const float* Pd = g_P + (size_t)d * ZP;
        const float* Ps = g_P + (size_t)s * ZP;
        float fd = __ldg(Pd + c);          // dst f (bias folded)
        float sd = __ldg(Pd + 256 + c);    // dst s (bias folded)
        float fs = __ldg(Ps + 128 + c);    // src f
        float ss = __ldg(Ps + 384 + c);    // src s

        ull FF = 0, SS = 0;   // (0.f, 0.f) packed
        FF = fma2(e0.x, wf2[0], FF);  SS = fma2(e0.x, ws2[0], SS);
        FF = fma2(e0.y, wf2[1], FF);  SS = fma2(e0.y, ws2[1], SS);
        FF = fma2(e1.x, wf2[2], FF);  SS = fma2(e1.x, ws2[2], SS);
        FF = fma2(e1.y, wf2[3], FF);  SS = fma2(e1.y, ws2[3], SS);
        FF = fma2(e2.x, wf2[4], FF);  SS = fma2(e2.x, ws2[4], SS);
        FF = fma2(e2.y, wf2[5], FF);  SS = fma2(e2.y, ws2[5], SS);
        FF = fma2(e3.x, wf2[6], FF);  SS = fma2(e3.x, ws2[6], SS);
        FF = fma2(e3.y, wf2[7], FF);  SS = fma2(e3.y, ws2[7], SS);

        float flo, fhi, slo, shi;
        unpack2(FF, flo, fhi);
        unpack2(SS, slo, shi);
        float F = fd + fs + flo + fhi;
        float S = sd + ss + slo + shi;
        float m = sigm(F) * sftp(S);

        float* outp = g_msg + (size_t)d * CC + c;
        asm volatile("red.global.add.f32 [%0], %1;"
                     :: "l"(outp), "f"(m) : "memory");
    }
}

// ---------------------------------------------------------------------------
__global__ void combine_k(const float* __restrict__ h, float* __restrict__ o,
                          int n4, int relu) {
    const float4* h4 = (const float4*)h;
    const float4* m4 = (const float4*)g_msg;
    float4* o4 = (float4*)o;
    for (int i = blockIdx.x * blockDim.x + threadIdx.x; i < n4;
         i += gridDim.x * blockDim.x) {
        float4 a = h4[i], b = m4[i];
        a.x += b.x; a.y += b.y; a.z += b.z; a.w += b.w;
        if (relu) {
            a.x = fmaxf(a.x, 0.f); a.y = fmaxf(a.y, 0.f);
            a.z = fmaxf(a.z, 0.f); a.w = fmaxf(a.w, 0.f);
        }
        o4[i] = a;
    }
}

// ---------------------------------------------------------------------------
__global__ void colsum_k(const float* __restrict__ h, int M) {
    int c = threadIdx.x;   // 128 threads
    float loc = 0.f;
    for (int i = blockIdx.x; i < M; i += gridDim.x)
        loc += h[(size_t)i * CC + c];
    atomicAdd(&g_cs[c], loc);
}

__global__ void final_k(const float* __restrict__ Wlin,
                        const float* __restrict__ blin,
                        float* __restrict__ out, float invM) {
    int o = threadIdx.x;
    if (o < 64) {
        float a = 0.f;
#pragma unroll 4
        for (int c = 0; c < 128; c++) a += g_cs[c] * Wlin[o * 128 + c];
        out[o] = blin[o] + a * invM;
    }
}

// ---------------------------------------------------------------------------
extern "C" void kernel_launch(void* const* d_in, const int* in_sizes, int n_in,
                              void* d_out, int out_size) {
    const float* x    = (const float*)d_in[0];
    const void*  eidx = d_in[1];
    const float* ew   = (const float*)d_in[2];
    const float* Wf[3] = {(const float*)d_in[3], (const float*)d_in[7],  (const float*)d_in[11]};
    const float* bf[3] = {(const float*)d_in[4], (const float*)d_in[8],  (const float*)d_in[12]};
    const float* Ws[3] = {(const float*)d_in[5], (const float*)d_in[9],  (const float*)d_in[13]};
    const float* bs[3] = {(const float*)d_in[6], (const float*)d_in[10], (const float*)d_in[14]};
    const float* Wlin = (const float*)d_in[15];
    const float* blin = (const float*)d_in[16];
    float* out = (float*)d_out;

    int M = in_sizes[0] / 128;   // 50000
    int E = in_sizes[2] / 16;    // 800000

    float *hA, *hB, *msg, *cs;
    cudaGetSymbolAddress((void**)&hA,  g_hA);
    cudaGetSymbolAddress((void**)&hB,  g_hB);
    cudaGetSymbolAddress((void**)&msg, g_msg);
    cudaGetSymbolAddress((void**)&cs,  g_cs);

    const float* hin[3]  = {x, hA, hB};
    float*       hout[3] = {hA, hB, hA};

    dim3 ggrid((M + 63) / 64, 8);
    int n4 = M * CC / 4;

    detect_k<<<1, 32>>>((const long long*)eidx, M);

    for (int l = 0; l < 3; l++) {
        pack_B<<<(ZP * CC + 255) / 256, 256>>>(Wf[l], Ws[l]);
        gemm_k<<<ggrid, 256>>>(hin[l], bf[l], bs[l], M);
        zero_k<<<1024, 256>>>(msg, n4);
        edge_k<<<2368, 256>>>(eidx, ew, Wf[l], Ws[l], E);
        combine_k<<<1024, 256>>>(hin[l], hout[l], n4, (l < 2) ? 1 : 0);
    }

    zero_k<<<1, 32>>>(cs, CC / 4);
    colsum_k<<<512, 128>>>(hA, M);
    final_k<<<1, 64>>>(Wlin, blin, out, 1.0f / (float)M);
}